// round 11
// baseline (speedup 1.0000x reference)
#include <cuda_runtime.h>

// Biquad DF2T, B=512, T=48000, fp32 — exact affine chunked scan,
// TIME-SEGMENTED for L2 residency of x.
//
//   P1(seg):   recurrence from z=0 per chunk -> aggregates w  (x read, default
//              policy -> allocates in L2; 31 MB per segment)
//   combine:   z_start[k+1] = A^C z_start[k] + w[k]  (A^C fp64, pipelined)
//   P3(seg):   recurrence from z_start, write y (.cs evict-first). x re-read
//              hits L2: between P1(s) and P3(s) at most ~62 MB flowed through
//              the 126 MB L2, so segment s's 31 MB of x is still resident.
//
// All global traffic coalesced float4; smem pad-33 tile transposes between
// I/O layout and lane-owns-a-channel compute layout (conflict-free).

#define B_CH   512
#define T_LEN  48000
#define C_LEN  160
#define K_CHK  300            // total chunks
#define NGR    5              // 32-sample groups per chunk
#define WPB    4
#define NGRP   16             // channel groups of 32
#define NSEG   3
#define K_SEG  (K_CHK / NSEG)              // 100 chunks per segment
#define NBLK_SEG ((NGRP * K_SEG) / WPB)    // 400 blocks per segment launch

__device__ float2 g_wz[K_CHK * B_CH];   // zero-state chunk-end states
__device__ float2 g_zs[K_CHK * B_CH];   // true chunk-start states

template <bool WRITE_Y>
__global__ __launch_bounds__(WPB * 32) void biquad_pass(
    const float* __restrict__ x,
    const float* __restrict__ b0p, const float* __restrict__ b1p,
    const float* __restrict__ b2p, const float* __restrict__ a1p,
    const float* __restrict__ a2p, float* __restrict__ out, int k0)
{
    __shared__ float tile[WPB][32][33];

    const int w    = threadIdx.x >> 5;
    const int lane = threadIdx.x & 31;
    const int wg   = blockIdx.x * WPB + w;
    const int cg   = wg & (NGRP - 1);
    const int k    = k0 + (wg >> 4);
    const int ch   = cg * 32 + lane;

    const float b0  = b0p[ch], b1 = b1p[ch], b2 = b2p[ch];
    const float na1 = -a1p[ch], na2 = -a2p[ch];

    float z1, z2;
    if (WRITE_Y) {
        const float2 zz = g_zs[k * B_CH + ch];
        z1 = zz.x; z2 = zz.y;
    } else {
        z1 = 0.0f; z2 = 0.0f;
    }

    const int lr = lane >> 3;          // 0..3
    const int lc = (lane & 7) * 4;     // 0..28
    const float* __restrict__ xbase = x + (size_t)(cg * 32) * T_LEN + k * C_LEN;
    float* __restrict__ obase = WRITE_Y
        ? out + (size_t)(cg * 32) * T_LEN + k * C_LEN : nullptr;

    auto ldx = [&](int g, int i) -> float4 {
        const float4* p = reinterpret_cast<const float4*>(
            xbase + (size_t)(i * 4 + lr) * T_LEN + g * 32 + lc);
        return WRITE_Y ? __ldcs(p) : *p;   // P3: last use -> evict-first
    };

    float4 r[8];
    #pragma unroll
    for (int i = 0; i < 8; i++) r[i] = ldx(0, i);

    #pragma unroll 1
    for (int g = 0; g < NGR; g++) {
        #pragma unroll
        for (int i = 0; i < 8; i++) {
            const int rr = i * 4 + lr;
            tile[w][rr][lc + 0] = r[i].x;
            tile[w][rr][lc + 1] = r[i].y;
            tile[w][rr][lc + 2] = r[i].z;
            tile[w][rr][lc + 3] = r[i].w;
        }
        __syncwarp();

        // Prefetch next group — these LDGs ride out the FMA chain.
        if (g + 1 < NGR) {
            #pragma unroll
            for (int i = 0; i < 8; i++) r[i] = ldx(g + 1, i);
        }

        #pragma unroll
        for (int j = 0; j < 32; j++) {
            const float xv = tile[w][lane][j];
            const float y  = fmaf(b0, xv, z1);
            const float t  = fmaf(b1, xv, z2);
            z1 = fmaf(na1, y, t);
            z2 = fmaf(na2, y, b2 * xv);
            if (WRITE_Y) tile[w][lane][j] = y;   // own row: no hazard
        }
        __syncwarp();

        if (WRITE_Y) {
            #pragma unroll
            for (int i = 0; i < 8; i++) {
                const int rr = i * 4 + lr;
                const float* src = &tile[w][rr][lc];
                float4 vv;
                vv.x = src[0]; vv.y = src[1]; vv.z = src[2]; vv.w = src[3];
                __stcs(reinterpret_cast<float4*>(
                    obase + (size_t)rr * T_LEN + g * 32 + lc), vv);
            }
            __syncwarp();
        }
    }

    if (!WRITE_Y) {
        g_wz[k * B_CH + ch] = make_float2(z1, z2);
    }
}

#define CB      15
#define NBATCH  (K_CHK / CB)       // 20 (even, required by pipeline)

__global__ void biquad_combine(const float* __restrict__ a1p,
                               const float* __restrict__ a2p)
{
    const int b = blockIdx.x * blockDim.x + threadIdx.x;
    if (b >= B_CH) return;

    const double a1 = (double)a1p[b];
    const double a2 = (double)a2p[b];

    // A = [[-a1, 1], [-a2, 0]]; A^C_LEN by repeated squaring in fp64.
    double r00 = 1.0, r01 = 0.0, r10 = 0.0, r11 = 1.0;
    double p00 = -a1, p01 = 1.0, p10 = -a2, p11 = 0.0;
    int e = C_LEN;
    while (e) {
        if (e & 1) {
            double n00 = r00*p00 + r01*p10, n01 = r00*p01 + r01*p11;
            double n10 = r10*p00 + r11*p10, n11 = r10*p01 + r11*p11;
            r00 = n00; r01 = n01; r10 = n10; r11 = n11;
        }
        e >>= 1;
        if (e) {
            double q00 = p00*p00 + p01*p10, q01 = p00*p01 + p01*p11;
            double q10 = p10*p00 + p11*p10, q11 = p10*p01 + p11*p11;
            p00 = q00; p01 = q01; p10 = q10; p11 = q11;
        }
    }
    const float m00 = (float)r00, m01 = (float)r01;
    const float m10 = (float)r10, m11 = (float)r11;

    float z1 = 0.0f, z2 = 0.0f;
    float2 wA[CB], wB[CB];

    auto loadb = [&](float2* buf, int t) {
        #pragma unroll
        for (int i = 0; i < CB; i++)
            buf[i] = g_wz[(t * CB + i) * B_CH + b];
    };
    auto procb = [&](const float2* buf, int t) {
        #pragma unroll
        for (int i = 0; i < CB; i++) {
            g_zs[(t * CB + i) * B_CH + b] = make_float2(z1, z2);
            const float n1 = fmaf(m00, z1, fmaf(m01, z2, buf[i].x));
            const float n2 = fmaf(m10, z1, fmaf(m11, z2, buf[i].y));
            z1 = n1; z2 = n2;
        }
    };

    // Software-pipelined: next batch's loads in flight during this batch's
    // dependent FMA chain.
    loadb(wA, 0);
    #pragma unroll 1
    for (int t = 0; t < NBATCH; t += 2) {
        loadb(wB, t + 1);
        procb(wA, t);
        if (t + 2 < NBATCH) loadb(wA, t + 2);
        procb(wB, t + 1);
    }
}

extern "C" void kernel_launch(void* const* d_in, const int* in_sizes, int n_in,
                              void* d_out, int out_size)
{
    const float* x  = (const float*)d_in[0];
    const float* b0 = (const float*)d_in[1];
    const float* b1 = (const float*)d_in[2];
    const float* b2 = (const float*)d_in[3];
    const float* a1 = (const float*)d_in[4];
    const float* a2 = (const float*)d_in[5];
    float* out = (float*)d_out;

    // Phase 1 over all segments (x streams into L2, 94 MB total < 126 MB).
    for (int s = 0; s < NSEG; s++)
        biquad_pass<false><<<NBLK_SEG, WPB * 32>>>(
            x, b0, b1, b2, a1, a2, nullptr, s * K_SEG);

    biquad_combine<<<16, 32>>>(a1, a2);

    // Phase 3 per segment: x_s still L2-resident (<= ~62 MB of intervening
    // traffic, and y writes are evict-first).
    for (int s = 0; s < NSEG; s++)
        biquad_pass<true><<<NBLK_SEG, WPB * 32>>>(
            x, b0, b1, b2, a1, a2, out, s * K_SEG);
}

// round 12
// speedup vs baseline: 1.3277x; 1.3277x over previous
#include <cuda_runtime.h>

// Biquad DF2T, B=512, T=48000, fp32 — exact affine chunked scan.
//   Pass 1: per (channel, chunk) recurrence from z=0 -> aggregate w[b][k]
//   Combine: WARP-PER-CHANNEL affine scan (this round's change):
//            lane l owns S=10 chunks -> local element (u_l, M^S); 5-step
//            shfl scan composes affine elements; lane replays its chunks.
//            (was: 16 serial warps, 14 us; now ~512-way parallel)
//   Pass 3: recurrence from z_start, write y (.cs).
// All global traffic coalesced float4; smem pad-33 transpose tiles.

#define B_CH   512
#define T_LEN  48000
#define C_LEN  160
#define K_CHK  300          // T_LEN / C_LEN
#define NGR    5            // 32-sample groups per chunk
#define WPB    4
#define NGRP   16           // channel groups of 32
#define NBLK   ((NGRP * K_CHK) / WPB)   // 1200
#define S_LANE 10           // chunks per lane in combine (32*10 >= 300)

__device__ float2 g_wz[K_CHK * B_CH];   // zero-state chunk-end states
__device__ float2 g_zs[K_CHK * B_CH];   // true chunk-start states

template <bool WRITE_Y>
__global__ __launch_bounds__(WPB * 32) void biquad_pass(
    const float* __restrict__ x,
    const float* __restrict__ b0p, const float* __restrict__ b1p,
    const float* __restrict__ b2p, const float* __restrict__ a1p,
    const float* __restrict__ a2p, float* __restrict__ out)
{
    __shared__ float tile[WPB][32][33];

    const int w    = threadIdx.x >> 5;
    const int lane = threadIdx.x & 31;
    const int wg   = blockIdx.x * WPB + w;
    const int cg   = wg & (NGRP - 1);
    const int k    = wg >> 4;
    const int ch   = cg * 32 + lane;

    const float b0  = b0p[ch], b1 = b1p[ch], b2 = b2p[ch];
    const float na1 = -a1p[ch], na2 = -a2p[ch];

    float z1, z2;
    if (WRITE_Y) {
        const float2 zz = g_zs[k * B_CH + ch];
        z1 = zz.x; z2 = zz.y;
    } else {
        z1 = 0.0f; z2 = 0.0f;
    }

    const int lr = lane >> 3;
    const int lc = (lane & 7) * 4;
    const float* __restrict__ xbase = x + (size_t)(cg * 32) * T_LEN + k * C_LEN;
    float* __restrict__ obase = WRITE_Y
        ? out + (size_t)(cg * 32) * T_LEN + k * C_LEN : nullptr;

    auto ldx = [&](int g, int i) -> float4 {
        const float4* p = reinterpret_cast<const float4*>(
            xbase + (size_t)(i * 4 + lr) * T_LEN + g * 32 + lc);
        return WRITE_Y ? __ldcs(p) : *p;
    };

    float4 r[8];
    #pragma unroll
    for (int i = 0; i < 8; i++) r[i] = ldx(0, i);

    #pragma unroll 1
    for (int g = 0; g < NGR; g++) {
        #pragma unroll
        for (int i = 0; i < 8; i++) {
            const int rr = i * 4 + lr;
            tile[w][rr][lc + 0] = r[i].x;
            tile[w][rr][lc + 1] = r[i].y;
            tile[w][rr][lc + 2] = r[i].z;
            tile[w][rr][lc + 3] = r[i].w;
        }
        __syncwarp();
        if (g + 1 < NGR) {
            #pragma unroll
            for (int i = 0; i < 8; i++) r[i] = ldx(g + 1, i);
        }
        #pragma unroll
        for (int j = 0; j < 32; j++) {
            const float xv = tile[w][lane][j];
            const float y  = fmaf(b0, xv, z1);
            const float t  = fmaf(b1, xv, z2);
            z1 = fmaf(na1, y, t);
            z2 = fmaf(na2, y, b2 * xv);
            if (WRITE_Y) tile[w][lane][j] = y;
        }
        __syncwarp();
        if (WRITE_Y) {
            #pragma unroll
            for (int i = 0; i < 8; i++) {
                const int rr = i * 4 + lr;
                const float* src = &tile[w][rr][lc];
                float4 vv;
                vv.x = src[0]; vv.y = src[1]; vv.z = src[2]; vv.w = src[3];
                __stcs(reinterpret_cast<float4*>(
                    obase + (size_t)rr * T_LEN + g * 32 + lc), vv);
            }
            __syncwarp();
        }
    }

    if (!WRITE_Y) {
        g_wz[k * B_CH + ch] = make_float2(z1, z2);
    }
}

// ── Combine: one warp per channel, affine warp scan ─────────────────────
__global__ __launch_bounds__(128) void biquad_combine(
    const float* __restrict__ a1p, const float* __restrict__ a2p)
{
    const int wid  = threadIdx.x >> 5;
    const int lane = threadIdx.x & 31;
    const int ch   = blockIdx.x * 4 + wid;        // 128 blocks * 4 warps = 512

    const double a1 = (double)a1p[ch];
    const double a2 = (double)a2p[ch];

    // M = A^C_LEN via repeated squaring (fp64); then Mp = M^S_LANE.
    double r00 = 1.0, r01 = 0.0, r10 = 0.0, r11 = 1.0;
    double p00 = -a1, p01 = 1.0, p10 = -a2, p11 = 0.0;
    int e = C_LEN;
    while (e) {
        if (e & 1) {
            double n00 = r00*p00 + r01*p10, n01 = r00*p01 + r01*p11;
            double n10 = r10*p00 + r11*p10, n11 = r10*p01 + r11*p11;
            r00 = n00; r01 = n01; r10 = n10; r11 = n11;
        }
        e >>= 1;
        if (e) {
            double q00 = p00*p00 + p01*p10, q01 = p00*p01 + p01*p11;
            double q10 = p10*p00 + p11*p10, q11 = p10*p01 + p11*p11;
            p00 = q00; p01 = q01; p10 = q10; p11 = q11;
        }
    }
    const float m00 = (float)r00, m01 = (float)r01;
    const float m10 = (float)r10, m11 = (float)r11;

    // Mp = M^S_LANE (fp64, from M): S=10 = 8+2.
    double s00 = r00, s01 = r01, s10 = r10, s11 = r11;   // M
    double t00, t01, t10, t11;
    // M^2
    t00 = s00*s00 + s01*s10; t01 = s00*s01 + s01*s11;
    t10 = s10*s00 + s11*s10; t11 = s10*s01 + s11*s11;
    // M^4
    double u00 = t00*t00 + t01*t10, u01 = t00*t01 + t01*t11;
    double u10 = t10*t00 + t11*t10, u11 = t10*t01 + t11*t11;
    // M^8
    double v00 = u00*u00 + u01*u10, v01 = u00*u01 + u01*u11;
    double v10 = u10*u00 + u11*u10, v11 = u10*u01 + u11*u11;
    // M^10 = M^8 * M^2
    const float q00 = (float)(v00*t00 + v01*t10);
    const float q01 = (float)(v00*t01 + v01*t11);
    const float q10 = (float)(v10*t00 + v11*t10);
    const float q11 = (float)(v10*t01 + v11*t11);

    // Lane's chunk range.
    const int k0  = lane * S_LANE;
    const int cnt = max(0, min(S_LANE, K_CHK - k0));   // 10 for lanes 0-29

    // Prefetch w for this lane's range (MLP), then local element u_l.
    float2 wv[S_LANE];
    #pragma unroll
    for (int i = 0; i < S_LANE; i++)
        if (i < cnt) wv[i] = g_wz[(k0 + i) * B_CH + ch];

    float uz1 = 0.0f, uz2 = 0.0f;
    #pragma unroll
    for (int i = 0; i < S_LANE; i++) {
        if (i < cnt) {
            const float n1 = fmaf(m00, uz1, fmaf(m01, uz2, wv[i].x));
            const float n2 = fmaf(m10, uz1, fmaf(m11, uz2, wv[i].y));
            uz1 = n1; uz2 = n2;
        }
    }

    // Lane element (u, P): P = M^cnt (I for empty lanes, M^10 for full).
    float P00, P01, P10, P11;
    if (cnt == S_LANE)      { P00 = q00; P01 = q01; P10 = q10; P11 = q11; }
    else                    { P00 = 1.f; P01 = 0.f; P10 = 0.f; P11 = 1.f; }
    // (K_CHK = 300 = 30 full lanes; lanes 30,31 are empty -> identity.)

    // Inclusive warp scan, affine composition: cur ∘ prev.
    float U1 = uz1, U2 = uz2;
    #pragma unroll
    for (int d = 1; d < 32; d <<= 1) {
        const float pu1 = __shfl_up_sync(0xffffffffu, U1, d);
        const float pu2 = __shfl_up_sync(0xffffffffu, U2, d);
        const float pp00 = __shfl_up_sync(0xffffffffu, P00, d);
        const float pp01 = __shfl_up_sync(0xffffffffu, P01, d);
        const float pp10 = __shfl_up_sync(0xffffffffu, P10, d);
        const float pp11 = __shfl_up_sync(0xffffffffu, P11, d);
        if (lane >= d) {
            U1 = fmaf(P00, pu1, fmaf(P01, pu2, U1));
            U2 = fmaf(P10, pu1, fmaf(P11, pu2, U2));
            const float n00 = fmaf(P00, pp00, P01 * pp10);
            const float n01 = fmaf(P00, pp01, P01 * pp11);
            const float n10 = fmaf(P10, pp00, P11 * pp10);
            const float n11 = fmaf(P10, pp01, P11 * pp11);
            P00 = n00; P01 = n01; P10 = n10; P11 = n11;
        }
    }

    // Exclusive prefix: z_in for this lane (z0 = 0 -> just the u-part).
    float zi1 = __shfl_up_sync(0xffffffffu, U1, 1);
    float zi2 = __shfl_up_sync(0xffffffffu, U2, 1);
    if (lane == 0) { zi1 = 0.0f; zi2 = 0.0f; }

    // Replay: store z_start for each owned chunk.
    float z1 = zi1, z2 = zi2;
    #pragma unroll
    for (int i = 0; i < S_LANE; i++) {
        if (i < cnt) {
            g_zs[(k0 + i) * B_CH + ch] = make_float2(z1, z2);
            const float n1 = fmaf(m00, z1, fmaf(m01, z2, wv[i].x));
            const float n2 = fmaf(m10, z1, fmaf(m11, z2, wv[i].y));
            z1 = n1; z2 = n2;
        }
    }
}

extern "C" void kernel_launch(void* const* d_in, const int* in_sizes, int n_in,
                              void* d_out, int out_size)
{
    const float* x  = (const float*)d_in[0];
    const float* b0 = (const float*)d_in[1];
    const float* b1 = (const float*)d_in[2];
    const float* b2 = (const float*)d_in[3];
    const float* a1 = (const float*)d_in[4];
    const float* a2 = (const float*)d_in[5];
    float* out = (float*)d_out;

    biquad_pass<false><<<NBLK, WPB * 32>>>(x, b0, b1, b2, a1, a2, nullptr);
    biquad_combine<<<B_CH / 4, 128>>>(a1, a2);
    biquad_pass<true><<<NBLK, WPB * 32>>>(x, b0, b1, b2, a1, a2, out);
}